// round 3
// baseline (speedup 1.0000x reference)
#include <cuda_runtime.h>
#include <cuda_fp16.h>
#include <math.h>

#define NN 50000
#define EE 800000
#define DIN 128
#define DH 64
#define DOUT 16
#define NCHUNK ((NN + 255) / 256)   // 196
#define EBLK ((EE + 255) / 256)     // 3125

// Scratch (device globals; no allocation allowed)
__device__ __align__(256) float g_h[NN * DH];        // fp32 activations (GEMM input)
__device__ __align__(256) __half g_th[NN * DH];      // fp16 gathered array (agg input)
__device__ float g_dinv[NN];
__device__ int g_cnt[NN];
__device__ int g_lexcl[NN];          // chunk-local exclusive scan of cnt
__device__ int g_rowptr[NN + 1];
__device__ int g_loc[EE];            // per-edge slot within its dst row
__device__ int g_col[EE];
__device__ int g_chtot[256];         // per-chunk totals (scanned redundantly per block)

// ---------------------------------------------------------------- preprocessing
// count degrees AND record each edge's local slot -> later non-atomic scatter
__global__ void k_count(const int* __restrict__ dst) {
    int i = blockIdx.x * blockDim.x + threadIdx.x;
    if (i < EE) g_loc[i] = atomicAdd(&g_cnt[dst[i]], 1);
}

// per-chunk scan (warp shuffles) + dinv fused in; writes chunk totals
__global__ void k_scan1() {
    __shared__ int wsum[8];
    int tid = threadIdx.x;
    int i = blockIdx.x * 256 + tid;
    int v = (i < NN) ? g_cnt[i] : 0;
    if (i < NN) g_dinv[i] = rsqrtf((float)(v + 1));  // +1 self loop
    int lane = tid & 31, w = tid >> 5;
    int incl = v;
#pragma unroll
    for (int o = 1; o < 32; o <<= 1) {
        int t = __shfl_up_sync(0xffffffffu, incl, o);
        if (lane >= o) incl += t;
    }
    if (lane == 31) wsum[w] = incl;
    __syncthreads();
    if (w == 0) {
        int s = (lane < 8) ? wsum[lane] : 0;
#pragma unroll
        for (int o = 1; o < 8; o <<= 1) {
            int t = __shfl_up_sync(0xffffffffu, s, o);
            if (lane >= o) s += t;
        }
        if (lane < 8) wsum[lane] = s;
    }
    __syncthreads();
    int woff = (w > 0) ? wsum[w - 1] : 0;
    if (i < NN) g_lexcl[i] = woff + incl - v;
    if (tid == 255) g_chtot[blockIdx.x] = woff + incl;
}

// redundant in-block scan of the 196 chunk totals -> exclusive offsets in smem
__device__ __forceinline__ void chunk_scan(int* soff) {
    __shared__ int wsum[8];
    int tid = threadIdx.x;
    int v = (tid < NCHUNK) ? g_chtot[tid] : 0;
    int lane = tid & 31, w = tid >> 5;
    int incl = v;
#pragma unroll
    for (int o = 1; o < 32; o <<= 1) {
        int t = __shfl_up_sync(0xffffffffu, incl, o);
        if (lane >= o) incl += t;
    }
    if (lane == 31) wsum[w] = incl;
    __syncthreads();
    if (w == 0) {
        int s = (lane < 8) ? wsum[lane] : 0;
#pragma unroll
        for (int o = 1; o < 8; o <<= 1) {
            int t = __shfl_up_sync(0xffffffffu, s, o);
            if (lane >= o) s += t;
        }
        if (lane < 8) wsum[lane] = s;
    }
    __syncthreads();
    int woff = (w > 0) ? wsum[w - 1] : 0;
    soff[tid] = woff + incl - v;  // exclusive
    __syncthreads();
}

// fused: finalize rowptr (blocks [0,NCHUNK)) + non-atomic CSR scatter (rest)
__global__ void k_finish(const int* __restrict__ src, const int* __restrict__ dst) {
    __shared__ int soff[256];
    chunk_scan(soff);
    int b = blockIdx.x;
    if (b < NCHUNK) {
        int i = b * 256 + threadIdx.x;
        if (i < NN) g_rowptr[i] = g_lexcl[i] + soff[b];
        if (b == 0 && threadIdx.x == 0) g_rowptr[NN] = EE;
    } else {
        int i = (b - NCHUNK) * 256 + threadIdx.x;
        if (i < EE) {
            int d = dst[i];
            g_col[g_lexcl[d] + soff[d >> 8] + g_loc[i]] = src[i];
        }
    }
}

// ---------------------------------------------------------------- dense GEMM [N,K]@[K,64] -> fp16 out
template <int K>
__global__ void k_gemm(const float* __restrict__ A, const float* __restrict__ W,
                       __half* __restrict__ C) {
    constexpr int PAD = 4;
    extern __shared__ float sm[];
    float* sW = sm;              // K*64
    float* sX = sm + K * 64;     // 64*(K+PAD)
    int tid = threadIdx.x;
    int base = blockIdx.x * 64;

    const float4* W4 = (const float4*)W;
    float4* sW4 = (float4*)sW;
    for (int i = tid; i < K * 16; i += 256) sW4[i] = W4[i];

    for (int i = tid; i < 64 * (K / 4); i += 256) {
        int r = i / (K / 4), kk = i % (K / 4);
        float4 v = make_float4(0.f, 0.f, 0.f, 0.f);
        if (base + r < NN) v = *(const float4*)(A + (size_t)(base + r) * K + kk * 4);
        *(float4*)(sX + r * (K + PAD) + kk * 4) = v;
    }
    __syncthreads();

    int tx = tid & 15, ty = tid >> 4;
    float acc[4][4];
#pragma unroll
    for (int i = 0; i < 4; i++)
#pragma unroll
        for (int j = 0; j < 4; j++) acc[i][j] = 0.f;

#pragma unroll 4
    for (int k = 0; k < K; k++) {
        float4 wv = *(const float4*)(sW + k * 64 + tx * 4);
#pragma unroll
        for (int i = 0; i < 4; i++) {
            float a = sX[(ty * 4 + i) * (K + PAD) + k];
            acc[i][0] = fmaf(a, wv.x, acc[i][0]);
            acc[i][1] = fmaf(a, wv.y, acc[i][1]);
            acc[i][2] = fmaf(a, wv.z, acc[i][2]);
            acc[i][3] = fmaf(a, wv.w, acc[i][3]);
        }
    }
#pragma unroll
    for (int i = 0; i < 4; i++) {
        int r = base + ty * 4 + i;
        if (r < NN) {
            __half2 h0 = __floats2half2_rn(acc[i][0], acc[i][1]);
            __half2 h1 = __floats2half2_rn(acc[i][2], acc[i][3]);
            __half2* p = (__half2*)(C + (size_t)r * DH + tx * 4);
            p[0] = h0;
            p[1] = h1;
        }
    }
}

// ------------------------------------------------------- aggregation + bias + ELU
// half2 per thread: 32 threads per node, 8 nodes per block; fp32 accumulate; fp32 out
__global__ void k_agg(const __half2* __restrict__ hin, float2* __restrict__ hout,
                      const float* __restrict__ bias) {
    int lane = threadIdx.x;               // 0..31 -> feature pair
    int node = blockIdx.x * 8 + threadIdx.y;
    if (node >= NN) return;
    float dd = g_dinv[node];
    int beg = g_rowptr[node], end = g_rowptr[node + 1];
    float2 hv = __half22float2(hin[(size_t)node * 32 + lane]);
    float2 acc = make_float2(hv.x * dd * dd, hv.y * dd * dd);  // self loop
    int k = beg;
    for (; k + 4 <= end; k += 4) {
        int j0 = g_col[k], j1 = g_col[k + 1], j2 = g_col[k + 2], j3 = g_col[k + 3];
        float n0 = g_dinv[j0] * dd, n1 = g_dinv[j1] * dd;
        float n2 = g_dinv[j2] * dd, n3 = g_dinv[j3] * dd;
        float2 h0 = __half22float2(hin[(size_t)j0 * 32 + lane]);
        float2 h1 = __half22float2(hin[(size_t)j1 * 32 + lane]);
        float2 h2 = __half22float2(hin[(size_t)j2 * 32 + lane]);
        float2 h3 = __half22float2(hin[(size_t)j3 * 32 + lane]);
        acc.x = fmaf(h0.x, n0, acc.x); acc.y = fmaf(h0.y, n0, acc.y);
        acc.x = fmaf(h1.x, n1, acc.x); acc.y = fmaf(h1.y, n1, acc.y);
        acc.x = fmaf(h2.x, n2, acc.x); acc.y = fmaf(h2.y, n2, acc.y);
        acc.x = fmaf(h3.x, n3, acc.x); acc.y = fmaf(h3.y, n3, acc.y);
    }
    for (; k < end; k++) {
        int j = g_col[k];
        float n = g_dinv[j] * dd;
        float2 h = __half22float2(hin[(size_t)j * 32 + lane]);
        acc.x = fmaf(h.x, n, acc.x);
        acc.y = fmaf(h.y, n, acc.y);
    }
    float2 bb = ((const float2*)bias)[lane];
    acc.x += bb.x;
    acc.y += bb.y;
    acc.x = (acc.x > 0.f) ? acc.x : expm1f(acc.x);
    acc.y = (acc.y > 0.f) ? acc.y : expm1f(acc.y);
    hout[(size_t)node * 32 + lane] = acc;
}

// ------------------------------------------------------- FC + softmax (warp per node)
__global__ void k_fc(const float* __restrict__ h, const float* __restrict__ fw,
                     const float* __restrict__ fb, float* __restrict__ out) {
    __shared__ float sW[DH * DOUT];
    __shared__ float sh[8][DH];
    for (int i = threadIdx.x; i < DH * DOUT; i += 256) sW[i] = fw[i];
    __syncthreads();
    int warp = threadIdx.x >> 5, lane = threadIdx.x & 31;
    int node = blockIdx.x * 8 + warp;
    if (node >= NN) return;
    sh[warp][lane] = h[(size_t)node * DH + lane];
    sh[warp][lane + 32] = h[(size_t)node * DH + lane + 32];
    __syncwarp();
    float v = 0.f;
    if (lane < DOUT) {
        v = fb[lane];
#pragma unroll
        for (int kk = 0; kk < DH; kk++) v = fmaf(sh[warp][kk], sW[kk * DOUT + lane], v);
    }
    float m = v;
#pragma unroll
    for (int o = 8; o; o >>= 1) m = fmaxf(m, __shfl_xor_sync(0xffffffffu, m, o, 16));
    float e = (lane < DOUT) ? expf(v - m) : 0.f;
    float s = e;
#pragma unroll
    for (int o = 8; o; o >>= 1) s += __shfl_xor_sync(0xffffffffu, s, o, 16);
    if (lane < DOUT) out[(size_t)node * DOUT + lane] = e / s;
}

// ---------------------------------------------------------------- launch
extern "C" void kernel_launch(void* const* d_in, const int* in_sizes, int n_in,
                              void* d_out, int out_size) {
    const float* x = (const float*)d_in[0];
    const int* ei = (const int*)d_in[1];   // [2, E] row-major
    const float* w0 = (const float*)d_in[2];
    const float* b0 = (const float*)d_in[3];
    const float* w1 = (const float*)d_in[4];
    const float* b1 = (const float*)d_in[5];
    const float* w2 = (const float*)d_in[6];
    const float* b2 = (const float*)d_in[7];
    const float* fw = (const float*)d_in[8];
    const float* fb = (const float*)d_in[9];
    float* out = (float*)d_out;
    const int* src = ei;
    const int* dst = ei + EE;

    float* p_h;
    __half* p_t;
    int* p_cnt;
    cudaGetSymbolAddress((void**)&p_h, g_h);
    cudaGetSymbolAddress((void**)&p_t, g_th);
    cudaGetSymbolAddress((void**)&p_cnt, g_cnt);

    const int smem128 = (128 * 64 + 64 * (128 + 4)) * 4;  // 66560 B
    const int smem64 = (64 * 64 + 64 * (64 + 4)) * 4;     // 33792 B
    cudaFuncSetAttribute(k_gemm<128>, cudaFuncAttributeMaxDynamicSharedMemorySize, smem128);
    cudaFuncSetAttribute(k_gemm<64>, cudaFuncAttributeMaxDynamicSharedMemorySize, smem64);

    // preprocessing (memset + 3 kernels)
    cudaMemsetAsync(p_cnt, 0, NN * sizeof(int));
    k_count<<<EBLK, 256>>>(dst);
    k_scan1<<<NCHUNK, 256>>>();
    k_finish<<<NCHUNK + EBLK, 256>>>(src, dst);

    const int gemm_grid = (NN + 63) / 64;
    const dim3 agg_block(32, 8);
    const int agg_grid = (NN + 7) / 8;

    // layer 0
    k_gemm<128><<<gemm_grid, 256, smem128>>>(x, w0, p_t);
    k_agg<<<agg_grid, agg_block>>>((const __half2*)p_t, (float2*)p_h, b0);
    // layer 1
    k_gemm<64><<<gemm_grid, 256, smem64>>>(p_h, w1, p_t);
    k_agg<<<agg_grid, agg_block>>>((const __half2*)p_t, (float2*)p_h, b1);
    // layer 2
    k_gemm<64><<<gemm_grid, 256, smem64>>>(p_h, w2, p_t);
    k_agg<<<agg_grid, agg_block>>>((const __half2*)p_t, (float2*)p_h, b2);
    // head
    k_fc<<<(NN + 7) / 8, 256>>>(p_h, fw, fb, out);
}

// round 4
// speedup vs baseline: 1.1274x; 1.1274x over previous
#include <cuda_runtime.h>
#include <cuda_fp16.h>
#include <math.h>
#include <stdint.h>

#define NN 50000
#define EE 800000
#define DIN 128
#define DH 64
#define DOUT 16
#define NCHUNK ((NN + 255) / 256)   // 196
#define EBLK ((EE + 255) / 256)     // 3125

// Scratch (device globals; no allocation allowed)
__device__ __align__(256) __half g_xh[NN * DIN];     // fp16 copy of x
__device__ __align__(256) __half g_th[NN * DH];      // GEMM out / agg in
__device__ __align__(256) __half g_ha[NN * DH];      // agg out / GEMM in / fc in
__device__ __align__(256) __half g_w0h[DIN * DH];
__device__ __align__(256) __half g_w1h[DH * DH];
__device__ __align__(256) __half g_w2h[DH * DH];
__device__ float g_dinv[NN];
__device__ int g_cnt[NN];
__device__ int g_lexcl[NN];
__device__ int g_rowptr[NN + 1];
__device__ int g_loc[EE];
__device__ int g_col[EE];
__device__ int g_chtot[256];

// ---------------------------------------------------------------- conversions
__global__ void k_cvt_x(const float4* __restrict__ x) {
    int i = blockIdx.x * blockDim.x + threadIdx.x;   // one float4 each
    if (i < NN * DIN / 4) {
        float4 v = x[i];
        __half2* p = (__half2*)(g_xh + (size_t)i * 4);
        p[0] = __floats2half2_rn(v.x, v.y);
        p[1] = __floats2half2_rn(v.z, v.w);
    }
}

__global__ void k_cvt_w(const float* __restrict__ w0, const float* __restrict__ w1,
                        const float* __restrict__ w2) {
    int i = blockIdx.x * blockDim.x + threadIdx.x;
    if (i < DIN * DH) g_w0h[i] = __float2half_rn(w0[i]);
    if (i < DH * DH) {
        g_w1h[i] = __float2half_rn(w1[i]);
        g_w2h[i] = __float2half_rn(w2[i]);
    }
}

// ---------------------------------------------------------------- preprocessing
__global__ void k_count(const int* __restrict__ dst) {
    int i = blockIdx.x * blockDim.x + threadIdx.x;
    if (i < EE) g_loc[i] = atomicAdd(&g_cnt[dst[i]], 1);
}

__global__ void k_scan1() {
    __shared__ int wsum[8];
    int tid = threadIdx.x;
    int i = blockIdx.x * 256 + tid;
    int v = (i < NN) ? g_cnt[i] : 0;
    if (i < NN) g_dinv[i] = rsqrtf((float)(v + 1));
    int lane = tid & 31, w = tid >> 5;
    int incl = v;
#pragma unroll
    for (int o = 1; o < 32; o <<= 1) {
        int t = __shfl_up_sync(0xffffffffu, incl, o);
        if (lane >= o) incl += t;
    }
    if (lane == 31) wsum[w] = incl;
    __syncthreads();
    if (w == 0) {
        int s = (lane < 8) ? wsum[lane] : 0;
#pragma unroll
        for (int o = 1; o < 8; o <<= 1) {
            int t = __shfl_up_sync(0xffffffffu, s, o);
            if (lane >= o) s += t;
        }
        if (lane < 8) wsum[lane] = s;
    }
    __syncthreads();
    int woff = (w > 0) ? wsum[w - 1] : 0;
    if (i < NN) g_lexcl[i] = woff + incl - v;
    if (tid == 255) g_chtot[blockIdx.x] = woff + incl;
}

__device__ __forceinline__ void chunk_scan(int* soff) {
    __shared__ int wsum[8];
    int tid = threadIdx.x;
    int v = (tid < NCHUNK) ? g_chtot[tid] : 0;
    int lane = tid & 31, w = tid >> 5;
    int incl = v;
#pragma unroll
    for (int o = 1; o < 32; o <<= 1) {
        int t = __shfl_up_sync(0xffffffffu, incl, o);
        if (lane >= o) incl += t;
    }
    if (lane == 31) wsum[w] = incl;
    __syncthreads();
    if (w == 0) {
        int s = (lane < 8) ? wsum[lane] : 0;
#pragma unroll
        for (int o = 1; o < 8; o <<= 1) {
            int t = __shfl_up_sync(0xffffffffu, s, o);
            if (lane >= o) s += t;
        }
        if (lane < 8) wsum[lane] = s;
    }
    __syncthreads();
    int woff = (w > 0) ? wsum[w - 1] : 0;
    soff[tid] = woff + incl - v;
    __syncthreads();
}

__global__ void k_finish(const int* __restrict__ src, const int* __restrict__ dst) {
    __shared__ int soff[256];
    chunk_scan(soff);
    int b = blockIdx.x;
    if (b < NCHUNK) {
        int i = b * 256 + threadIdx.x;
        if (i < NN) g_rowptr[i] = g_lexcl[i] + soff[b];
        if (b == 0 && threadIdx.x == 0) g_rowptr[NN] = EE;
    } else {
        int i = (b - NCHUNK) * 256 + threadIdx.x;
        if (i < EE) {
            int d = dst[i];
            g_col[g_lexcl[d] + soff[d >> 8] + g_loc[i]] = src[i];
        }
    }
}

// ---------------------------------------------------------------- tensor-core GEMM
// C[N,64] = A[N,K] @ W[K,64], fp16 in, fp32 accum, fp16 out.
// Block: 256 threads (8 warps), tile 128 rows x 64 cols. Warp w -> rows [16w,16w+16).
__device__ __forceinline__ void mma16816(float* d, uint32_t a0, uint32_t a1,
                                         uint32_t a2, uint32_t a3, uint32_t b0,
                                         uint32_t b1) {
    asm volatile(
        "mma.sync.aligned.m16n8k16.row.col.f32.f16.f16.f32 "
        "{%0,%1,%2,%3}, {%4,%5,%6,%7}, {%8,%9}, {%0,%1,%2,%3};\n"
        : "+f"(d[0]), "+f"(d[1]), "+f"(d[2]), "+f"(d[3])
        : "r"(a0), "r"(a1), "r"(a2), "r"(a3), "r"(b0), "r"(b1));
}

template <int K>
__global__ void k_gemm(const __half* __restrict__ A, const __half* __restrict__ W,
                       __half* __restrict__ C) {
    constexpr int LDA = K + 8;       // halves
    constexpr int LDB = K + 8;
    extern __shared__ __half sm[];
    __half* sA = sm;                 // 128 x LDA
    __half* sB = sm + 128 * LDA;     // 64 x LDB  (W transposed: sB[n][k])
    int tid = threadIdx.x;
    int warp = tid >> 5, lane = tid & 31;
    int base = blockIdx.x * 128;

    // load A tile (128 x K halves) as uint4 (8 halves)
    constexpr int RV = K / 8;        // uint4 per row
    for (int i = tid; i < 128 * RV; i += 256) {
        int r = i / RV, c = i % RV;
        uint4 v = make_uint4(0u, 0u, 0u, 0u);
        if (base + r < NN) v = *(const uint4*)(A + (size_t)(base + r) * K + c * 8);
        *(uint4*)(sA + r * LDA + c * 8) = v;
    }
    // load W transposed: sB[n*LDB + k] = W[k*64 + n]
    for (int i = tid; i < K * 64; i += 256) {
        int k = i >> 6, n = i & 63;
        sB[n * LDB + k] = W[i];
    }
    __syncthreads();

    int grp = lane >> 2, tig = lane & 3;
    int rowA = warp * 16 + grp;
    float acc[8][4];
#pragma unroll
    for (int j = 0; j < 8; j++)
#pragma unroll
        for (int q = 0; q < 4; q++) acc[j][q] = 0.f;

#pragma unroll
    for (int kc = 0; kc < K; kc += 16) {
        uint32_t a0 = *(const uint32_t*)(sA + rowA * LDA + kc + 2 * tig);
        uint32_t a1 = *(const uint32_t*)(sA + (rowA + 8) * LDA + kc + 2 * tig);
        uint32_t a2 = *(const uint32_t*)(sA + rowA * LDA + kc + 2 * tig + 8);
        uint32_t a3 = *(const uint32_t*)(sA + (rowA + 8) * LDA + kc + 2 * tig + 8);
#pragma unroll
        for (int j = 0; j < 8; j++) {
            uint32_t b0 = *(const uint32_t*)(sB + (j * 8 + grp) * LDB + kc + 2 * tig);
            uint32_t b1 = *(const uint32_t*)(sB + (j * 8 + grp) * LDB + kc + 2 * tig + 8);
            mma16816(acc[j], a0, a1, a2, a3, b0, b1);
        }
    }

    int r0 = base + rowA, r1 = r0 + 8;
#pragma unroll
    for (int j = 0; j < 8; j++) {
        int col = j * 8 + 2 * tig;
        if (r0 < NN)
            *(__half2*)(C + (size_t)r0 * DH + col) = __floats2half2_rn(acc[j][0], acc[j][1]);
        if (r1 < NN)
            *(__half2*)(C + (size_t)r1 * DH + col) = __floats2half2_rn(acc[j][2], acc[j][3]);
    }
}

// ------------------------------------------------------- aggregation + bias + ELU
// half2 in, fp32 accumulate, half2 out
__global__ void k_agg(const __half2* __restrict__ hin, __half2* __restrict__ hout,
                      const float* __restrict__ bias) {
    int lane = threadIdx.x;
    int node = blockIdx.x * 8 + threadIdx.y;
    if (node >= NN) return;
    float dd = g_dinv[node];
    int beg = g_rowptr[node], end = g_rowptr[node + 1];
    float2 hv = __half22float2(hin[(size_t)node * 32 + lane]);
    float2 acc = make_float2(hv.x * dd * dd, hv.y * dd * dd);
    int k = beg;
    for (; k + 4 <= end; k += 4) {
        int j0 = g_col[k], j1 = g_col[k + 1], j2 = g_col[k + 2], j3 = g_col[k + 3];
        float n0 = g_dinv[j0] * dd, n1 = g_dinv[j1] * dd;
        float n2 = g_dinv[j2] * dd, n3 = g_dinv[j3] * dd;
        float2 h0 = __half22float2(hin[(size_t)j0 * 32 + lane]);
        float2 h1 = __half22float2(hin[(size_t)j1 * 32 + lane]);
        float2 h2 = __half22float2(hin[(size_t)j2 * 32 + lane]);
        float2 h3 = __half22float2(hin[(size_t)j3 * 32 + lane]);
        acc.x = fmaf(h0.x, n0, acc.x); acc.y = fmaf(h0.y, n0, acc.y);
        acc.x = fmaf(h1.x, n1, acc.x); acc.y = fmaf(h1.y, n1, acc.y);
        acc.x = fmaf(h2.x, n2, acc.x); acc.y = fmaf(h2.y, n2, acc.y);
        acc.x = fmaf(h3.x, n3, acc.x); acc.y = fmaf(h3.y, n3, acc.y);
    }
    for (; k < end; k++) {
        int j = g_col[k];
        float n = g_dinv[j] * dd;
        float2 h = __half22float2(hin[(size_t)j * 32 + lane]);
        acc.x = fmaf(h.x, n, acc.x);
        acc.y = fmaf(h.y, n, acc.y);
    }
    float2 bb = ((const float2*)bias)[lane];
    acc.x += bb.x;
    acc.y += bb.y;
    acc.x = (acc.x > 0.f) ? acc.x : expm1f(acc.x);
    acc.y = (acc.y > 0.f) ? acc.y : expm1f(acc.y);
    hout[(size_t)node * 32 + lane] = __floats2half2_rn(acc.x, acc.y);
}

// ------------------------------------------------------- FC + softmax (warp per node)
__global__ void k_fc(const __half2* __restrict__ h, const float* __restrict__ fw,
                     const float* __restrict__ fb, float* __restrict__ out) {
    __shared__ float sW[DH * DOUT];
    __shared__ float sh[8][DH];
    for (int i = threadIdx.x; i < DH * DOUT; i += 256) sW[i] = fw[i];
    __syncthreads();
    int warp = threadIdx.x >> 5, lane = threadIdx.x & 31;
    int node = blockIdx.x * 8 + warp;
    if (node >= NN) return;
    float2 hv = __half22float2(h[(size_t)node * 32 + lane]);
    sh[warp][2 * lane] = hv.x;
    sh[warp][2 * lane + 1] = hv.y;
    __syncwarp();
    float v = 0.f;
    if (lane < DOUT) {
        v = fb[lane];
#pragma unroll
        for (int kk = 0; kk < DH; kk++) v = fmaf(sh[warp][kk], sW[kk * DOUT + lane], v);
    }
    float m = v;
#pragma unroll
    for (int o = 8; o; o >>= 1) m = fmaxf(m, __shfl_xor_sync(0xffffffffu, m, o, 16));
    float e = (lane < DOUT) ? expf(v - m) : 0.f;
    float s = e;
#pragma unroll
    for (int o = 8; o; o >>= 1) s += __shfl_xor_sync(0xffffffffu, s, o, 16);
    if (lane < DOUT) out[(size_t)node * DOUT + lane] = e / s;
}

// ---------------------------------------------------------------- launch
extern "C" void kernel_launch(void* const* d_in, const int* in_sizes, int n_in,
                              void* d_out, int out_size) {
    const float* x = (const float*)d_in[0];
    const int* ei = (const int*)d_in[1];
    const float* w0 = (const float*)d_in[2];
    const float* b0 = (const float*)d_in[3];
    const float* w1 = (const float*)d_in[4];
    const float* b1 = (const float*)d_in[5];
    const float* w2 = (const float*)d_in[6];
    const float* b2 = (const float*)d_in[7];
    const float* fw = (const float*)d_in[8];
    const float* fb = (const float*)d_in[9];
    float* out = (float*)d_out;
    const int* src = ei;
    const int* dst = ei + EE;

    __half *p_xh, *p_t, *p_ha, *p_w0, *p_w1, *p_w2;
    int* p_cnt;
    cudaGetSymbolAddress((void**)&p_xh, g_xh);
    cudaGetSymbolAddress((void**)&p_t, g_th);
    cudaGetSymbolAddress((void**)&p_ha, g_ha);
    cudaGetSymbolAddress((void**)&p_w0, g_w0h);
    cudaGetSymbolAddress((void**)&p_w1, g_w1h);
    cudaGetSymbolAddress((void**)&p_w2, g_w2h);
    cudaGetSymbolAddress((void**)&p_cnt, g_cnt);

    const int smem128 = (128 * (128 + 8) + 64 * (128 + 8)) * 2;  // 52224 B
    const int smem64 = (128 * (64 + 8) + 64 * (64 + 8)) * 2;     // 27648 B
    cudaFuncSetAttribute(k_gemm<128>, cudaFuncAttributeMaxDynamicSharedMemorySize, smem128);
    cudaFuncSetAttribute(k_gemm<64>, cudaFuncAttributeMaxDynamicSharedMemorySize, smem64);

    // conversions
    k_cvt_w<<<(DIN * DH + 255) / 256, 256>>>(w0, w1, w2);
    k_cvt_x<<<(NN * DIN / 4 + 255) / 256, 256>>>((const float4*)x);

    // preprocessing
    cudaMemsetAsync(p_cnt, 0, NN * sizeof(int));
    k_count<<<EBLK, 256>>>(dst);
    k_scan1<<<NCHUNK, 256>>>();
    k_finish<<<NCHUNK + EBLK, 256>>>(src, dst);

    const int gemm_grid = (NN + 127) / 128;
    const dim3 agg_block(32, 8);
    const int agg_grid = (NN + 7) / 8;

    // layer 0
    k_gemm<128><<<gemm_grid, 256, smem128>>>(p_xh, p_w0, p_t);
    k_agg<<<agg_grid, agg_block>>>((const __half2*)p_t, (__half2*)p_ha, b0);
    // layer 1
    k_gemm<64><<<gemm_grid, 256, smem64>>>(p_ha, p_w1, p_t);
    k_agg<<<agg_grid, agg_block>>>((const __half2*)p_t, (__half2*)p_ha, b1);
    // layer 2
    k_gemm<64><<<gemm_grid, 256, smem64>>>(p_ha, p_w2, p_t);
    k_agg<<<agg_grid, agg_block>>>((const __half2*)p_t, (__half2*)p_ha, b2);
    // head
    k_fc<<<(NN + 7) / 8, 256>>>((const __half2*)p_ha, fw, fb, out);
}